// round 8
// baseline (speedup 1.0000x reference)
#include <cuda_runtime.h>
#include <math.h>

typedef unsigned long long U64;
typedef long long i64;

namespace cfg {
constexpr int B = 256, T = 128, H = 512, L = 4, NT = 74;
constexpr int BH = B * H;
constexpr i64 BTH = (i64)B * T * H;
constexpr i64 O_X = 0;
constexpr i64 O_Y = O_X + BTH;
constexpr i64 O_N = O_Y + BTH;
constexpr i64 O_Q = O_N + BTH;
constexpr i64 O_K = O_Q + BTH;
constexpr i64 O_V = O_K + BTH;
constexpr i64 O_AO = O_V + BTH;
constexpr i64 O_S = O_AO + BTH;              // [B,T,T]
constexpr i64 O_LG = O_S + (i64)B * T * T;   // logits
constexpr i64 O_HB = O_LG + (i64)B * T * NT; // h ping-pong [2][L][BH]
constexpr i64 O_CB = O_HB + 2LL * L * BH;    // c [L][BH]
constexpr i64 O_NLL = O_CB + 2LL * L * BH;
constexpr i64 O_VLD = O_NLL + B * T;
constexpr i64 TOT = O_VLD + B * T;
}
__device__ float g_buf[cfg::TOT];

__device__ __forceinline__ U64 ffma2(U64 a, U64 b, U64 c) {
    U64 d; asm("fma.rn.f32x2 %0, %1, %2, %3;" : "=l"(d) : "l"(a), "l"(b), "l"(c));
    return d;
}
__device__ __forceinline__ float hsum2(U64 v) {
    float lo, hi; asm("mov.b64 {%0,%1}, %2;" : "=f"(lo), "=f"(hi) : "l"(v));
    return lo + hi;
}
__device__ __forceinline__ float sigf(float x) { return 1.f / (1.f + __expf(-x)); }

__device__ __forceinline__ float4 ldcg4(const float* p) {
    float4 v;
    asm volatile("ld.global.cg.v4.f32 {%0,%1,%2,%3}, [%4];"
                 : "=f"(v.x), "=f"(v.y), "=f"(v.z), "=f"(v.w) : "l"(p));
    return v;
}

__device__ __forceinline__ void cluster_bar() {
    asm volatile("barrier.cluster.arrive.aligned;" ::: "memory");
    asm volatile("barrier.cluster.wait.aligned;" ::: "memory");
}

// ---------------- cluster-persistent LSTM ----------------
// 16 clusters x 8 CTAs. Cluster = 16 batch rows; CTA rank owns 64 h-cols
// (256 gate-cols). 128 threads: mg=tid>>5 (4 row-groups), ng=tid&31.
// Per-thread 4 rows x (4 gates x 2 j). c is CTA-private (never crosses CTAs).
__global__ void __launch_bounds__(128) __cluster_dims__(8, 1, 1) lstm_cluster(
    const float* __restrict__ x, float* __restrict__ y,
    float* __restrict__ hb, float* __restrict__ cbuf,
    const float* __restrict__ eWih, const float* __restrict__ eWhh,
    const float* __restrict__ ebih, const float* __restrict__ ebhh,
    const float* __restrict__ dWih, const float* __restrict__ dWhh,
    const float* __restrict__ dbih, const float* __restrict__ dbhh)
{
    using namespace cfg;
    constexpr int RS = 18;             // smem row stride (16 k + pad 2)
    constexpr int BUF = 272 * RS;      // 256 W rows + 16 A rows
    __shared__ float sm[2 * BUF];      // 39168 B, double-buffered
    const int tid = threadIdx.x;
    const int mg = tid >> 5, ng = tid & 31;
    const int rank = blockIdx.x & 7;
    const int r0 = (blockIdx.x >> 3) * 16;

    // zero own c slice and own h parity-1 slice
#pragma unroll
    for (int l = 0; l < 4; ++l)
#pragma unroll
        for (int bb = 0; bb < 4; ++bb)
#pragma unroll
            for (int jj = 0; jj < 2; ++jj) {
                i64 off = (i64)l * BH + (i64)(r0 + mg * 4 + bb) * H + rank * 64 + ng + jj * 32;
                cbuf[off] = 0.f;
                hb[(i64)L * BH + off] = 0.f;
            }
    __threadfence();
    cluster_bar();

    for (int tt = 0; tt < 2 * T; ++tt) {
        const int p = tt & 1;
        const bool enc = tt < T;
        const float* Wih = enc ? eWih : dWih;
        const float* Whh = enc ? eWhh : dWhh;
        const float* bih = enc ? ebih : dbih;
        const float* bhh = enc ? ebhh : dbhh;
        for (int l = 0; l < 4; ++l) {
            const float* xin;
            if (l)            xin = hb + (i64)p * L * BH + (i64)(l - 1) * BH;
            else if (enc)     xin = x + (i64)tt * BH;
            else if (tt == T) xin = hb + (i64)L * BH + 3LL * BH;
            else              xin = y + (i64)(tt - T - 1) * BH;
            const float* hp = hb + (i64)(1 - p) * L * BH + (i64)l * BH;
            float* ho = hb + (i64)p * L * BH + (i64)l * BH;
            float* yo = (!enc && l == 3) ? (y + (i64)(tt - T) * BH) : nullptr;
            const float* Wi = Wih + (i64)l * 2048 * 512;
            const float* Wh = Whh + (i64)l * 2048 * 512;

            U64 acc[4][8];
#pragma unroll
            for (int bb = 0; bb < 4; ++bb)
#pragma unroll
                for (int q = 0; q < 8; ++q) acc[bb][q] = 0ull;

            float4 pw[8], pa;
            // prefetch chunk 0
#pragma unroll
            for (int i = 0; i < 8; ++i) {
                int lin = tid + i * 128, n = lin >> 2, c4 = (lin & 3) * 4;
                int wrow = ((n >> 6) << 9) + rank * 64 + (n & 63);
                pw[i] = *(const float4*)&Wi[(i64)wrow * 512 + c4];
            }
            if (tid < 64) {
                int row = tid >> 2, c4 = (tid & 3) * 4;
                pa = ldcg4(&xin[(i64)(r0 + row) * 512 + c4]);
            }

            for (int s = 0; s < 64; ++s) {
                float* buf = sm + (s & 1) * BUF;
#pragma unroll
                for (int i = 0; i < 8; ++i) {
                    int lin = tid + i * 128, n = lin >> 2, c4 = (lin & 3) * 4;
                    float* d = &buf[n * RS + c4];
                    d[0] = pw[i].x; d[1] = pw[i].y; d[2] = pw[i].z; d[3] = pw[i].w;
                }
                if (tid < 64) {
                    int row = tid >> 2, c4 = (tid & 3) * 4;
                    float* d = &buf[(256 + row) * RS + c4];
                    d[0] = pa.x; d[1] = pa.y; d[2] = pa.z; d[3] = pa.w;
                }
                __syncthreads();
                if (s < 63) {
                    const int sn = s + 1;
                    const float* A = (sn < 32) ? xin : hp;
                    const float* W = (sn < 32) ? Wi : Wh;
                    const int k0 = (sn & 31) * 16;
#pragma unroll
                    for (int i = 0; i < 8; ++i) {
                        int lin = tid + i * 128, n = lin >> 2, c4 = (lin & 3) * 4;
                        int wrow = ((n >> 6) << 9) + rank * 64 + (n & 63);
                        pw[i] = *(const float4*)&W[(i64)wrow * 512 + k0 + c4];
                    }
                    if (tid < 64) {
                        int row = tid >> 2, c4 = (tid & 3) * 4;
                        pa = ldcg4(&A[(i64)(r0 + row) * 512 + k0 + c4]);
                    }
                }
                const U64* wb = (const U64*)buf;
#pragma unroll
                for (int kp = 0; kp < 8; ++kp) {
                    U64 wv[8];
#pragma unroll
                    for (int g = 0; g < 4; ++g) {
                        wv[g * 2 + 0] = wb[(g * 64 + ng) * 9 + kp];
                        wv[g * 2 + 1] = wb[(g * 64 + 32 + ng) * 9 + kp];
                    }
#pragma unroll
                    for (int bb = 0; bb < 4; ++bb) {
                        U64 av = wb[(256 + mg * 4 + bb) * 9 + kp];
#pragma unroll
                        for (int q = 0; q < 8; ++q)
                            acc[bb][q] = ffma2(av, wv[q], acc[bb][q]);
                    }
                }
            }

            const float* bi = bih + (i64)l * 2048;
            const float* bh2 = bhh + (i64)l * 2048;
#pragma unroll
            for (int bb = 0; bb < 4; ++bb) {
                const int b = r0 + mg * 4 + bb;
#pragma unroll
                for (int jj = 0; jj < 2; ++jj) {
                    const int col = rank * 64 + ng + jj * 32;
                    float gi = hsum2(acc[bb][0 + jj]) + bi[col] + bh2[col];
                    float gf = hsum2(acc[bb][2 + jj]) + bi[512 + col] + bh2[512 + col];
                    float gg = hsum2(acc[bb][4 + jj]) + bi[1024 + col] + bh2[1024 + col];
                    float go = hsum2(acc[bb][6 + jj]) + bi[1536 + col] + bh2[1536 + col];
                    i64 ci = (i64)l * BH + (i64)b * H + col;
                    float cn = sigf(gf) * cbuf[ci] + sigf(gi) * tanhf(gg);
                    float hn = sigf(go) * tanhf(cn);
                    cbuf[ci] = cn;
                    ho[(i64)b * H + col] = hn;
                    if (yo) yo[(i64)b * H + col] = hn;
                }
            }
            __threadfence();
            cluster_bar();
        }
    }
}

// ---------------- generic GEMM: C = alpha*A@W^T + bias (transW optional) -----
__global__ void __launch_bounds__(128) gemm2_kernel(
    const float* __restrict__ A1, const float* __restrict__ W1,
    const float* __restrict__ bias, float* __restrict__ C,
    int M, int N, int K, int ldw, float alpha, int transW,
    i64 sA, i64 sW, i64 sC)
{
    __shared__ float a_s[64 * 34];
    __shared__ float w_s[64 * 34];
    const int tid = threadIdx.x;
    const int ng = tid & 15, mg = tid >> 4;
    const int m0 = blockIdx.x * 64, n0 = blockIdx.y * 64;
    const float* A = A1 + (i64)blockIdx.z * sA;
    const float* W = W1 + (i64)blockIdx.z * sW;
    float* Cb = C + (i64)blockIdx.z * sC;

    U64 acc[8][4];
#pragma unroll
    for (int mm = 0; mm < 8; ++mm)
#pragma unroll
        for (int nn = 0; nn < 4; ++nn) acc[mm][nn] = 0ull;

    for (int kc = 0; kc < K; kc += 32) {
        __syncthreads();
#pragma unroll
        for (int i = 0; i < 4; ++i) {
            int lin = tid + i * 128;
            int row = lin >> 3, c4 = (lin & 7) * 4;
            float4 v = *(const float4*)&A[(i64)(m0 + row) * K + kc + c4];
            float* d = &a_s[row * 34 + c4];
            d[0] = v.x; d[1] = v.y; d[2] = v.z; d[3] = v.w;
        }
        if (!transW) {
#pragma unroll
            for (int i = 0; i < 4; ++i) {
                int lin = tid + i * 128;
                int row = lin >> 3, c4 = (lin & 7) * 4;
                float4 v = make_float4(0.f, 0.f, 0.f, 0.f);
                if (n0 + row < N) v = *(const float4*)&W[(i64)(n0 + row) * ldw + kc + c4];
                float* d = &w_s[row * 34 + c4];
                d[0] = v.x; d[1] = v.y; d[2] = v.z; d[3] = v.w;
            }
        } else {
#pragma unroll
            for (int i = 0; i < 4; ++i) {
                int lin = tid + i * 128;
                int kk = lin >> 4, c4 = (lin & 15) * 4;
                float4 v = *(const float4*)&W[(i64)(kc + kk) * ldw + n0 + c4];
                w_s[(c4 + 0) * 34 + kk] = v.x;
                w_s[(c4 + 1) * 34 + kk] = v.y;
                w_s[(c4 + 2) * 34 + kk] = v.z;
                w_s[(c4 + 3) * 34 + kk] = v.w;
            }
        }
        __syncthreads();
#pragma unroll
        for (int kp = 0; kp < 16; ++kp) {
            U64 wv[4];
#pragma unroll
            for (int nn = 0; nn < 4; ++nn)
                wv[nn] = *(const U64*)&w_s[(ng + nn * 16) * 34 + kp * 2];
#pragma unroll
            for (int mm = 0; mm < 8; ++mm) {
                U64 av = *(const U64*)&a_s[(mg * 8 + mm) * 34 + kp * 2];
#pragma unroll
                for (int nn = 0; nn < 4; ++nn)
                    acc[mm][nn] = ffma2(av, wv[nn], acc[mm][nn]);
            }
        }
    }
#pragma unroll
    for (int mm = 0; mm < 8; ++mm) {
        const int m = m0 + mg * 8 + mm;
#pragma unroll
        for (int nn = 0; nn < 4; ++nn) {
            const int n = n0 + ng + nn * 16;
            if (n < N) {
                float v = hsum2(acc[mm][nn]) * alpha;
                if (bias) v += bias[n];
                Cb[(i64)m * N + n] = v;
            }
        }
    }
}

// ---------------- small kernels ----------------
__global__ void embed_kernel(const int* __restrict__ ids, const float* __restrict__ emb,
                             float* __restrict__ x) {
    int bid = blockIdx.x;              // b*T + t
    int b = bid >> 7, t = bid & 127;
    i64 id = ids[bid];
    const float4* s = (const float4*)(emb + id * cfg::H);
    float4* d = (float4*)(x + (i64)t * cfg::BH + (i64)b * cfg::H);
    d[threadIdx.x] = s[threadIdx.x];
}

__global__ void __launch_bounds__(128) ln_kernel(const float* __restrict__ y,
    const float* __restrict__ gam, const float* __restrict__ bet, float* __restrict__ out)
{
    using namespace cfg;
    int r = blockIdx.x;                 // t*B + b
    int t = r >> 8, bi = r & 255;
    int h = threadIdx.x * 4;
    float4 v = *(const float4*)&y[(i64)r * H + h];
    float s = v.x + v.y + v.z + v.w;
    float sq = v.x * v.x + v.y * v.y + v.z * v.z + v.w * v.w;
#pragma unroll
    for (int o = 16; o > 0; o >>= 1) {
        s += __shfl_xor_sync(0xffffffffu, s, o);
        sq += __shfl_xor_sync(0xffffffffu, sq, o);
    }
    __shared__ float ss[4], sqs[4];
    if ((threadIdx.x & 31) == 0) { ss[threadIdx.x >> 5] = s; sqs[threadIdx.x >> 5] = sq; }
    __syncthreads();
    s = ss[0] + ss[1] + ss[2] + ss[3];
    sq = sqs[0] + sqs[1] + sqs[2] + sqs[3];
    float mu = s * (1.f / 512.f);
    float rstd = rsqrtf(sq * (1.f / 512.f) - mu * mu + 1e-5f);
    float4 g4 = *(const float4*)&gam[h];
    float4 b4 = *(const float4*)&bet[h];
    float4 o;
    o.x = (v.x - mu) * rstd * g4.x + b4.x;
    o.y = (v.y - mu) * rstd * g4.y + b4.y;
    o.z = (v.z - mu) * rstd * g4.z + b4.z;
    o.w = (v.w - mu) * rstd * g4.w + b4.w;
    *(float4*)&out[(i64)bi * T * H + (i64)t * H + h] = o;
}

__global__ void softmax128_kernel(float* __restrict__ S) {
    float* row = S + (i64)blockIdx.x * 128;
    int tid = threadIdx.x;
    float v = row[tid];
    __shared__ float r1[4], r2[4];
    float m = v;
#pragma unroll
    for (int o = 16; o > 0; o >>= 1) m = fmaxf(m, __shfl_xor_sync(0xffffffffu, m, o));
    if ((tid & 31) == 0) r1[tid >> 5] = m;
    __syncthreads();
    m = fmaxf(fmaxf(r1[0], r1[1]), fmaxf(r1[2], r1[3]));
    float e = __expf(v - m), s = e;
#pragma unroll
    for (int o = 16; o > 0; o >>= 1) s += __shfl_xor_sync(0xffffffffu, s, o);
    if ((tid & 31) == 0) r2[tid >> 5] = s;
    __syncthreads();
    s = r2[0] + r2[1] + r2[2] + r2[3];
    row[tid] = e / s;
}

__global__ void tag_softmax_kernel(const float* __restrict__ logits,
    const int* __restrict__ tag_ids, float* __restrict__ prob,
    float* __restrict__ nll, float* __restrict__ valid)
{
    using namespace cfg;
    int r = blockIdx.x;
    int tid = threadIdx.x;
    const float* lr = logits + (i64)r * NT;
    float v = (tid < NT) ? lr[tid] : -1e30f;
    __shared__ float r1[4], r2[4];
    float m = v;
#pragma unroll
    for (int o = 16; o > 0; o >>= 1) m = fmaxf(m, __shfl_xor_sync(0xffffffffu, m, o));
    if ((tid & 31) == 0) r1[tid >> 5] = m;
    __syncthreads();
    m = fmaxf(fmaxf(r1[0], r1[1]), fmaxf(r1[2], r1[3]));
    float e = (tid < NT) ? __expf(v - m) : 0.f, s = e;
#pragma unroll
    for (int o = 16; o > 0; o >>= 1) s += __shfl_xor_sync(0xffffffffu, s, o);
    if ((tid & 31) == 0) r2[tid >> 5] = s;
    __syncthreads();
    s = r2[0] + r2[1] + r2[2] + r2[3];
    if (tid < NT) prob[(i64)r * NT + tid] = e / s;
    if (tid == 0) {
        int tg = tag_ids[r];
        float n = -(lr[tg] - m - __logf(s));
        float vl = (tg != 0) ? 1.f : 0.f;
        nll[r] = n * vl; valid[r] = vl;
    }
}

__global__ void loss_kernel(const float* __restrict__ nll, const float* __restrict__ valid,
                            float* __restrict__ out) {
    __shared__ float sn[256], sv[256];
    int tid = threadIdx.x;
    float a = 0.f, b = 0.f;
    for (int i = tid; i < cfg::B * cfg::T; i += 256) { a += nll[i]; b += valid[i]; }
    sn[tid] = a; sv[tid] = b;
    __syncthreads();
    for (int st = 128; st > 0; st >>= 1) {
        if (tid < st) { sn[tid] += sn[tid + st]; sv[tid] += sv[tid + st]; }
        __syncthreads();
    }
    if (tid == 0) out[0] = sn[0] / fmaxf(sv[0], 1.f);
}

// ---------------- host orchestration ----------------
extern "C" void kernel_launch(void* const* d_in, const int*, int, void* d_out, int) {
    using namespace cfg;
    const int* ids = (const int*)d_in[0];
    const int* tags = (const int*)d_in[1];
    const float* emb = (const float*)d_in[3];
    const float* eWih = (const float*)d_in[4];
    const float* eWhh = (const float*)d_in[5];
    const float* ebih = (const float*)d_in[6];
    const float* ebhh = (const float*)d_in[7];
    const float* dWih = (const float*)d_in[8];
    const float* dWhh = (const float*)d_in[9];
    const float* dbih = (const float*)d_in[10];
    const float* dbhh = (const float*)d_in[11];
    const float* ln_g = (const float*)d_in[12];
    const float* ln_b = (const float*)d_in[13];
    const float* Wq = (const float*)d_in[14];
    const float* bq = (const float*)d_in[15];
    const float* Wk = (const float*)d_in[16];
    const float* bk = (const float*)d_in[17];
    const float* Wv = (const float*)d_in[18];
    const float* bv = (const float*)d_in[19];
    const float* Wtag = (const float*)d_in[20];
    const float* btag = (const float*)d_in[21];

    float* buf = nullptr;
    cudaGetSymbolAddress((void**)&buf, g_buf);
    float* x = buf + O_X;  float* y = buf + O_Y;   float* nrm = buf + O_N;
    float* q = buf + O_Q;  float* kx = buf + O_K;  float* vx = buf + O_V;
    float* ao = buf + O_AO; float* sc = buf + O_S; float* lg = buf + O_LG;
    float* hb = buf + O_HB; float* cb = buf + O_CB;
    float* nllp = buf + O_NLL; float* vldp = buf + O_VLD;

    embed_kernel<<<B * T, 128>>>(ids, emb, x);
    lstm_cluster<<<128, 128>>>(x, y, hb, cb, eWih, eWhh, ebih, ebhh,
                               dWih, dWhh, dbih, dbhh);
    ln_kernel<<<T * B, 128>>>(y, ln_g, ln_b, nrm);

    const int Mq = B * T;  // 32768
    gemm2_kernel<<<dim3(Mq / 64, 8, 1), 128>>>(nrm, Wq, bq, q, Mq, 512, 512, 512,
                                               1.f, 0, 0, 0, 0);
    gemm2_kernel<<<dim3(Mq / 64, 8, 1), 128>>>(nrm, Wk, bk, kx, Mq, 512, 512, 512,
                                               1.f, 0, 0, 0, 0);
    gemm2_kernel<<<dim3(Mq / 64, 8, 1), 128>>>(nrm, Wv, bv, vx, Mq, 512, 512, 512,
                                               1.f, 0, 0, 0, 0);
    gemm2_kernel<<<dim3(2, 2, B), 128>>>(q, kx, nullptr, sc, 128, 128, 512, 512,
        0.044194173824159216f, 0, (i64)T * H, (i64)T * H, (i64)T * T);
    softmax128_kernel<<<B * T, 128>>>(sc);
    gemm2_kernel<<<dim3(2, 8, B), 128>>>(sc, vx, nullptr, ao, 128, 512, 128, 512,
        1.f, 1, (i64)T * T, (i64)T * H, (i64)T * H);
    gemm2_kernel<<<dim3(Mq / 64, 2, 1), 128>>>(ao, Wtag, btag, lg, Mq, NT, 512, 512,
                                               1.f, 0, 0, 0, 0);
    tag_softmax_kernel<<<B * T, 128>>>(lg, tags, (float*)d_out, nllp, vldp);
    loss_kernel<<<1, 256>>>(nllp, vldp, (float*)d_out + (i64)B * T * NT);
}